// round 15
// baseline (speedup 1.0000x reference)
#include <cuda_runtime.h>
#include <math.h>
#include <stdint.h>

// DPLSTMCell row-0, R15: R14 (8.67us, 2 outputs/block) -> 4 outputs/block.
// 256 blocks, block b computes n = b + 256*o, o=0..3.
//   warps 0-3: Wih rows (gate=wid) for 4 outputs via interleaved LDG.128;
//              one vector chunk feeds 4 FMA groups (4 independent weight streams).
//   warps 4-7: Whh rows (gate=wid-4) for 4 outputs via cp.async.cg (32 ops, 16KB in flight).
// Per-output vector traffic and reduce/epilogue cost quartered. 64KB dynamic smem,
// 2 blocks/SM. Fast MUFU epilogue. No .nc/evict/TMA/front-batch (proven regressions).

#define H 1024
#define D 1024
#define NBLK 256
#define NO 4

__device__ __forceinline__ float warp_reduce(float v) {
    #pragma unroll
    for (int off = 16; off > 0; off >>= 1)
        v += __shfl_xor_sync(0xFFFFFFFFu, v, off);
    return v;
}

__device__ __forceinline__ float fast_tanh(float x) {
    float r;
    asm("tanh.approx.f32 %0, %1;" : "=f"(r) : "f"(x));
    return r;
}
__device__ __forceinline__ float fast_sigmoid(float x) {
    return 0.5f * fast_tanh(0.5f * x) + 0.5f;
}

__global__ __launch_bounds__(256)
void lstm_row0_x4_kernel(const float* __restrict__ x,
                         const float* __restrict__ h,
                         const float* __restrict__ c_prev,
                         const float* __restrict__ Wih,
                         const float* __restrict__ Whh,
                         const float* __restrict__ bih,
                         const float* __restrict__ bhh,
                         float* __restrict__ out) {
    // swh[gate][o][256 float4] : 4*4*4KB = 64KB (dynamic)
    extern __shared__ float4 swh[];
    __shared__ float sums[NO][8];

    const int bid  = blockIdx.x;
    const int tid  = threadIdx.x;
    const int wid  = tid >> 5;
    const int lane = tid & 31;

    float acc[NO] = {0.f, 0.f, 0.f, 0.f};

    if (wid >= 4) {
        // ---- async path: Whh rows for gate = wid-4, outputs o=0..3 ----
        const int gate = wid - 4;
        float4* sbase = &swh[gate * NO * 256];
        #pragma unroll
        for (int o = 0; o < NO; o++) {
            const int n = bid + NBLK * o;
            const float* src = Whh + (size_t)(gate * H + n) * D;
            #pragma unroll
            for (int i = 0; i < 8; i++) {
                const int idx = lane + i * 32;
                const uint32_t dst = (uint32_t)__cvta_generic_to_shared(
                    &sbase[o * 256 + idx]);
                asm volatile("cp.async.cg.shared.global [%0], [%1], 16;"
                             :: "r"(dst), "l"(src + idx * 4) : "memory");
            }
        }
        asm volatile("cp.async.commit_group;" ::: "memory");

        // Vector h (L1/L2-hot) overlaps the async transfers; reused 4x.
        const float4* __restrict__ v4 = reinterpret_cast<const float4*>(h);
        float4 vr[8];
        #pragma unroll
        for (int i = 0; i < 8; i++)
            vr[i] = v4[lane + i * 32];

        asm volatile("cp.async.wait_group 0;" ::: "memory");
        __syncwarp();

        #pragma unroll
        for (int i = 0; i < 8; i++) {
            const int idx = lane + i * 32;
            #pragma unroll
            for (int o = 0; o < NO; o++) {
                const float4 wv = sbase[o * 256 + idx];
                acc[o] += wv.x * vr[i].x + wv.y * vr[i].y
                        + wv.z * vr[i].z + wv.w * vr[i].w;
            }
        }
    } else {
        // ---- LDG path: Wih rows for gate = wid, 4 outputs, interleaved ----
        const int gate = wid;
        const float4* __restrict__ w0 = reinterpret_cast<const float4*>(
            Wih + (size_t)(gate * H + bid) * D);
        const float4* __restrict__ w1 = reinterpret_cast<const float4*>(
            Wih + (size_t)(gate * H + bid + NBLK) * D);
        const float4* __restrict__ w2 = reinterpret_cast<const float4*>(
            Wih + (size_t)(gate * H + bid + 2 * NBLK) * D);
        const float4* __restrict__ w3 = reinterpret_cast<const float4*>(
            Wih + (size_t)(gate * H + bid + 3 * NBLK) * D);
        const float4* __restrict__ v4 = reinterpret_cast<const float4*>(x);
        #pragma unroll
        for (int i = 0; i < 8; i++) {
            const int idx = lane + i * 32;
            const float4 a = w0[idx];
            const float4 b = w1[idx];
            const float4 c = w2[idx];
            const float4 d = w3[idx];
            const float4 xv = v4[idx];
            acc[0] += a.x * xv.x + a.y * xv.y + a.z * xv.z + a.w * xv.w;
            acc[1] += b.x * xv.x + b.y * xv.y + b.z * xv.z + b.w * xv.w;
            acc[2] += c.x * xv.x + c.y * xv.y + c.z * xv.z + c.w * xv.w;
            acc[3] += d.x * xv.x + d.y * xv.y + d.z * xv.z + d.w * xv.w;
        }
    }

    #pragma unroll
    for (int o = 0; o < NO; o++) {
        acc[o] = warp_reduce(acc[o]);
        if (lane == 0) sums[o][wid] = acc[o];
    }
    __syncthreads();

    // Four epilogues on four lanes of warp 0 (independent).
    if (tid < NO) {
        const int o = tid;
        const int n = bid + NBLK * o;
        // sums[o][g] = Wih·x gate g ; sums[o][4+g] = Whh·h gate g
        float gi = sums[o][0] + sums[o][4] + bih[n]         + bhh[n];
        float gf = sums[o][1] + sums[o][5] + bih[H + n]     + bhh[H + n];
        float gg = sums[o][2] + sums[o][6] + bih[2 * H + n] + bhh[2 * H + n];
        float go = sums[o][3] + sums[o][7] + bih[3 * H + n] + bhh[3 * H + n];

        float i_t = fast_sigmoid(gi);
        float f_t = fast_sigmoid(gf);
        float g_t = fast_tanh(gg);
        float o_t = fast_sigmoid(go);

        float c_t = f_t * c_prev[n] + i_t * g_t;
        out[n] = o_t * fast_tanh(c_t);
    }
}

extern "C" void kernel_launch(void* const* d_in, const int* in_sizes, int n_in,
                              void* d_out, int out_size) {
    const float* x      = (const float*)d_in[0];
    const float* h      = (const float*)d_in[1];
    const float* c_prev = (const float*)d_in[2];
    const float* Wih    = (const float*)d_in[3];
    const float* Whh    = (const float*)d_in[4];
    const float* bih    = (const float*)d_in[5];
    const float* bhh    = (const float*)d_in[6];
    float* out = (float*)d_out;

    static int smem_set = 0;
    if (!smem_set) {
        cudaFuncSetAttribute(lstm_row0_x4_kernel,
                             cudaFuncAttributeMaxDynamicSharedMemorySize,
                             64 * 1024);
        smem_set = 1;
    }
    lstm_row0_x4_kernel<<<NBLK, 256, 64 * 1024>>>(
        x, h, c_prev, Wih, Whh, bih, bhh, out);
}